// round 8
// baseline (speedup 1.0000x reference)
#include <cuda_runtime.h>

#define D    128
#define KNEI 32

// One block per output row n.
// 128 threads = 4 warps; warp w handles neighbors k = w*8 .. w*8+7.
// Neighbor embeddings are staged in SMEM during the score pass so the
// weighted-sum pass never re-touches L2 (halves gather traffic).
__global__ __launch_bounds__(128, 8)
void gat_attn_kernel(const int*   __restrict__ nei,      // int32! (JAX x64 disabled)
                     const float* __restrict__ h,
                     const float* __restrict__ h_refer,
                     const float* __restrict__ att,
                     float*       __restrict__ out,
                     int N)
{
    __shared__ float s_emb[KNEI][D];   // 16 KB: gathered neighbor tile
    __shared__ float s_score[KNEI];
    __shared__ float s_w[KNEI];

    const int n = blockIdx.x;
    if (n >= N) return;
    const int tid  = threadIdx.x;
    const int lane = tid & 31;
    const int warp = tid >> 5;

    // att layout: [0..D) = att_ref, [D..2D) = att_nei. Each lane owns float4
    // covering elements lane*4 .. lane*4+3.
    const float4 aref = reinterpret_cast<const float4*>(att)[lane];
    const float4 anei = reinterpret_cast<const float4*>(att)[32 + lane];

    // s_ref = h_refer[n] . att_ref  (computed redundantly per warp — 1 KB read)
    const float4 hr = reinterpret_cast<const float4*>(h_refer + (size_t)n * D)[lane];
    float sref = fmaf(hr.x, aref.x, fmaf(hr.y, aref.y, fmaf(hr.z, aref.z, hr.w * aref.w)));
    #pragma unroll
    for (int o = 16; o; o >>= 1)
        sref += __shfl_xor_sync(0xffffffffu, sref, o);

    // Each warp's 8 neighbor indices: lanes 0..7 load, broadcast via shfl.
    int myidx = 0;
    if (lane < 8)
        myidx = nei[(size_t)n * KNEI + warp * 8 + lane];

    #pragma unroll
    for (int j = 0; j < 8; ++j) {
        const int k = warp * 8 + j;
        const int idx = __shfl_sync(0xffffffffu, myidx, j);
        const float4 v = reinterpret_cast<const float4*>(h + (size_t)idx * D)[lane];
        reinterpret_cast<float4*>(&s_emb[k][0])[lane] = v;  // stage for pass 2
        float p = fmaf(v.x, anei.x, fmaf(v.y, anei.y, fmaf(v.z, anei.z, v.w * anei.w)));
        #pragma unroll
        for (int o = 16; o; o >>= 1)
            p += __shfl_xor_sync(0xffffffffu, p, o);
        if (lane == 0) {
            const float s = sref + p;
            s_score[k] = (s >= 0.0f) ? s : 0.01f * s;   // leaky_relu(0.01)
        }
    }
    __syncthreads();

    // Softmax over K=32 by warp 0.
    if (warp == 0) {
        const float s = s_score[lane];
        float m = s;
        #pragma unroll
        for (int o = 16; o; o >>= 1)
            m = fmaxf(m, __shfl_xor_sync(0xffffffffu, m, o));
        const float e = expf(s - m);
        float sum = e;
        #pragma unroll
        for (int o = 16; o; o >>= 1)
            sum += __shfl_xor_sync(0xffffffffu, sum, o);
        s_w[lane] = e / sum;
    }
    __syncthreads();

    // out[n][tid] = sum_k w[k] * emb[k][tid]; lanes read consecutive words
    // of each SMEM row -> conflict-free; 512 B coalesced store per block.
    float acc = 0.0f;
    #pragma unroll
    for (int k = 0; k < KNEI; ++k)
        acc = fmaf(s_w[k], s_emb[k][tid], acc);
    out[(size_t)n * D + tid] = acc;
}

extern "C" void kernel_launch(void* const* d_in, const int* in_sizes, int n_in,
                              void* d_out, int out_size)
{
    const int*   nei     = (const int*)d_in[0];    // int32 [N, 32] (x64 disabled in JAX)
    const float* h       = (const float*)d_in[1];  // f32   [M, 128]
    const float* h_refer = (const float*)d_in[2];  // f32   [N, 128]
    const float* att     = (const float*)d_in[3];  // f32   [1, 256]
    float*       out     = (float*)d_out;          // f32   [N, 128]

    const int N = in_sizes[0] / KNEI;
    gat_attn_kernel<<<N, 128>>>(nei, h, h_refer, att, out, N);
}

// round 9
// speedup vs baseline: 1.3968x; 1.3968x over previous
#include <cuda_runtime.h>

#define D    128
#define KNEI 32

// One block (128 thr, 4 warps) per output row n. Warp w owns neighbors
// k = w*8 .. w*8+7 and keeps their gathered float4s IN REGISTERS across the
// softmax, so the weighted-sum pass touches neither L2 nor a big SMEM tile.
// Cross-warp combine uses a 2 KB partial buffer.
__global__ __launch_bounds__(128)
void gat_attn_kernel(const int*   __restrict__ nei,      // int32 (JAX x64 off)
                     const float* __restrict__ h,
                     const float* __restrict__ h_refer,
                     const float* __restrict__ att,
                     float*       __restrict__ out,
                     int N)
{
    __shared__ float s_score[KNEI];      // raw neighbor dot (pre-ref, pre-leaky)
    __shared__ float s_w[KNEI];          // softmax weights
    __shared__ float s_part[4][D];       // per-warp partial weighted sums (2 KB)

    const int n = blockIdx.x;
    if (n >= N) return;
    const int tid  = threadIdx.x;
    const int lane = tid & 31;
    const int warp = tid >> 5;

    // att layout: [0..D)=att_ref, [D..2D)=att_nei; lane owns elements lane*4..+3
    const float4 anei = reinterpret_cast<const float4*>(att)[32 + lane];

    // Warp's 8 neighbor indices: lanes 0..7 load, broadcast via shfl.
    int myidx = 0;
    if (lane < 8)
        myidx = nei[(size_t)n * KNEI + warp * 8 + lane];
    int idxv[8];
    #pragma unroll
    for (int j = 0; j < 8; ++j)
        idxv[j] = __shfl_sync(0xffffffffu, myidx, j);

    // Batch all 8 gathers first -> 8 outstanding LDG.128 per lane (MLP=8).
    float4 v[8];
    #pragma unroll
    for (int j = 0; j < 8; ++j)
        v[j] = reinterpret_cast<const float4*>(h + (size_t)idxv[j] * D)[lane];

    // Raw scores p_k = h[idx_k] . att_nei  (ref term added by warp 0 later).
    #pragma unroll
    for (int j = 0; j < 8; ++j) {
        float p = fmaf(v[j].x, anei.x,
                  fmaf(v[j].y, anei.y,
                  fmaf(v[j].z, anei.z, v[j].w * anei.w)));
        #pragma unroll
        for (int o = 16; o; o >>= 1)
            p += __shfl_xor_sync(0xffffffffu, p, o);
        if (lane == 0)
            s_score[warp * 8 + j] = p;
    }

    // Warp 0 alone computes sref = h_refer[n] . att_ref (kept in registers
    // across the sync; same warp does the softmax).
    float sref = 0.0f;
    if (warp == 0) {
        const float4 aref = reinterpret_cast<const float4*>(att)[lane];
        const float4 hr   = reinterpret_cast<const float4*>(h_refer + (size_t)n * D)[lane];
        sref = fmaf(hr.x, aref.x, fmaf(hr.y, aref.y, fmaf(hr.z, aref.z, hr.w * aref.w)));
        #pragma unroll
        for (int o = 16; o; o >>= 1)
            sref += __shfl_xor_sync(0xffffffffu, sref, o);
    }
    __syncthreads();

    // Softmax over K=32 by warp 0 (leaky_relu applied to sref + p).
    if (warp == 0) {
        float s = sref + s_score[lane];
        s = (s >= 0.0f) ? s : 0.01f * s;
        float m = s;
        #pragma unroll
        for (int o = 16; o; o >>= 1)
            m = fmaxf(m, __shfl_xor_sync(0xffffffffu, m, o));
        const float e = expf(s - m);
        float sum = e;
        #pragma unroll
        for (int o = 16; o; o >>= 1)
            sum += __shfl_xor_sync(0xffffffffu, sum, o);
        s_w[lane] = e / sum;
    }
    __syncthreads();

    // Per-warp weighted partial sum straight from registers.
    float4 acc = make_float4(0.f, 0.f, 0.f, 0.f);
    #pragma unroll
    for (int j = 0; j < 8; ++j) {
        const float w = s_w[warp * 8 + j];   // LDS broadcast
        acc.x = fmaf(w, v[j].x, acc.x);
        acc.y = fmaf(w, v[j].y, acc.y);
        acc.z = fmaf(w, v[j].z, acc.z);
        acc.w = fmaf(w, v[j].w, acc.w);
    }
    reinterpret_cast<float4*>(&s_part[warp][0])[lane] = acc;
    __syncthreads();

    // Combine 4 warp partials; coalesced 512 B store per block.
    const float r = s_part[0][tid] + s_part[1][tid] + s_part[2][tid] + s_part[3][tid];
    out[(size_t)n * D + tid] = r;
}

extern "C" void kernel_launch(void* const* d_in, const int* in_sizes, int n_in,
                              void* d_out, int out_size)
{
    const int*   nei     = (const int*)d_in[0];    // int32 [N, 32]
    const float* h       = (const float*)d_in[1];  // f32   [M, 128]
    const float* h_refer = (const float*)d_in[2];  // f32   [N, 128]
    const float* att     = (const float*)d_in[3];  // f32   [1, 256]
    float*       out     = (float*)d_out;          // f32   [N, 128]

    const int N = in_sizes[0] / KNEI;
    gat_attn_kernel<<<N, 128>>>(nei, h, h_refer, att, out, N);
}

// round 10
// speedup vs baseline: 2.2985x; 1.6455x over previous
#include <cuda_runtime.h>

#define D        128
#define KNEI     32
#define MAXROWS  50176   // >= max(N, M) = 50000

// Scratch (no cudaMalloc allowed): precomputed row dots.
__device__ float g_hn[MAXROWS];   // hn[m] = h[m]        . att[D..2D)
__device__ float g_hr[MAXROWS];   // hr[n] = h_refer[n]  . att[0..D)

// ---------------------------------------------------------------------------
// Pass 1: streaming row-dot precompute. One warp per row; rows [0,M) -> g_hn,
// rows [M, M+N) -> g_hr. Pure bandwidth (~51 MB read).
// ---------------------------------------------------------------------------
__global__ __launch_bounds__(256)
void precompute_dots(const float* __restrict__ h,
                     const float* __restrict__ h_refer,
                     const float* __restrict__ att,
                     int M, int N)
{
    const int gw   = (blockIdx.x * blockDim.x + threadIdx.x) >> 5;
    const int lane = threadIdx.x & 31;
    if (gw >= M + N) return;

    const bool is_h = (gw < M);
    const float* src = is_h ? (h + (size_t)gw * D)
                            : (h_refer + (size_t)(gw - M) * D);
    const float4 a = reinterpret_cast<const float4*>(att)[(is_h ? 32 : 0) + lane];
    const float4 v = reinterpret_cast<const float4*>(src)[lane];

    float p = fmaf(v.x, a.x, fmaf(v.y, a.y, fmaf(v.z, a.z, v.w * a.w)));
    #pragma unroll
    for (int o = 16; o; o >>= 1)
        p += __shfl_xor_sync(0xffffffffu, p, o);

    if (lane == 0) {
        if (is_h) g_hn[gw] = p;
        else      g_hr[gw - M] = p;
    }
}

// ---------------------------------------------------------------------------
// Pass 2: warp-autonomous row kernel. One warp per output row:
//   lane k: idx_k = nei[n][k]; score_k = leaky(hr[n] + hn[idx_k])
//   warp softmax -> w_k (stored to 128B SMEM per warp)
//   weighted streaming gather: acc[lane*4..+3] += w_k * h[idx_k][lane*4..+3]
// No __syncthreads, no cross-warp traffic, tiny register footprint.
// ---------------------------------------------------------------------------
__global__ __launch_bounds__(256)
void gat_main(const int*   __restrict__ nei,
              const float* __restrict__ h,
              float*       __restrict__ out,
              int N)
{
    __shared__ int   s_idx[8][KNEI];
    __shared__ float s_w[8][KNEI];

    const int warp = threadIdx.x >> 5;
    const int lane = threadIdx.x & 31;
    const int n    = blockIdx.x * 8 + warp;
    if (n >= N) return;

    // 128B coalesced index load; scattered 4B score-gather from L2-hot hn.
    const int idx = nei[(size_t)n * KNEI + lane];
    float s = g_hr[n] + g_hn[idx];
    s = (s >= 0.0f) ? s : 0.01f * s;          // leaky_relu(0.01)

    float m = s;
    #pragma unroll
    for (int o = 16; o; o >>= 1)
        m = fmaxf(m, __shfl_xor_sync(0xffffffffu, m, o));
    const float e = __expf(s - m);
    float sum = e;
    #pragma unroll
    for (int o = 16; o; o >>= 1)
        sum += __shfl_xor_sync(0xffffffffu, sum, o);

    s_w[warp][lane]   = e / sum;
    s_idx[warp][lane] = idx;
    __syncwarp();

    // Streaming weighted gather: weights known up-front, nothing held across
    // a softmax. Full unroll -> ptxas batches LDG.128s (deep MLP).
    float4 acc = make_float4(0.f, 0.f, 0.f, 0.f);
    #pragma unroll
    for (int k = 0; k < KNEI; ++k) {
        const float  wk = s_w[warp][k];                       // LDS broadcast
        const float4 v  = reinterpret_cast<const float4*>(
                              h + (size_t)s_idx[warp][k] * D)[lane];
        acc.x = fmaf(wk, v.x, acc.x);
        acc.y = fmaf(wk, v.y, acc.y);
        acc.z = fmaf(wk, v.z, acc.z);
        acc.w = fmaf(wk, v.w, acc.w);
    }
    reinterpret_cast<float4*>(out + (size_t)n * D)[lane] = acc;   // 512B store
}

extern "C" void kernel_launch(void* const* d_in, const int* in_sizes, int n_in,
                              void* d_out, int out_size)
{
    const int*   nei     = (const int*)d_in[0];    // int32 [N, 32]
    const float* h       = (const float*)d_in[1];  // f32   [M, 128]
    const float* h_refer = (const float*)d_in[2];  // f32   [N, 128]
    const float* att     = (const float*)d_in[3];  // f32   [1, 256]
    float*       out     = (float*)d_out;          // f32   [N, 128]

    const int N = in_sizes[0] / KNEI;
    const int M = in_sizes[1] / D;

    const int totalWarps = M + N;
    const int preBlocks  = (totalWarps + 7) / 8;        // 8 warps / 256-thr block
    precompute_dots<<<preBlocks, 256>>>(h, h_refer, att, M, N);

    const int mainBlocks = (N + 7) / 8;                 // 8 rows / block
    gat_main<<<mainBlocks, 256>>>(nei, h, out, N);
}

// round 11
// speedup vs baseline: 2.5667x; 1.1167x over previous
#include <cuda_runtime.h>

#define D        128
#define KNEI     32
#define MAXROWS  50176   // >= M = 50000

// Scratch (no cudaMalloc allowed): precomputed neighbor-side row dots.
__device__ float g_hn[MAXROWS];   // hn[m] = h[m] . att[D..2D)

// ---------------------------------------------------------------------------
// Pass 1: hn[m] = h[m] . att_nei  (M rows only; h_refer dot is fused in main).
// One warp per row; pure streaming (~25.6 MB read).
// ---------------------------------------------------------------------------
__global__ __launch_bounds__(256)
void precompute_hn(const float* __restrict__ h,
                   const float* __restrict__ att,
                   int M)
{
    const int gw   = (blockIdx.x * blockDim.x + threadIdx.x) >> 5;
    const int lane = threadIdx.x & 31;
    if (gw >= M) return;

    const float4 a = reinterpret_cast<const float4*>(att)[32 + lane];
    const float4 v = reinterpret_cast<const float4*>(h + (size_t)gw * D)[lane];

    float p = fmaf(v.x, a.x, fmaf(v.y, a.y, fmaf(v.z, a.z, v.w * a.w)));
    #pragma unroll
    for (int o = 16; o; o >>= 1)
        p += __shfl_xor_sync(0xffffffffu, p, o);
    if (lane == 0) g_hn[gw] = p;
}

// ---------------------------------------------------------------------------
// Pass 2: warp-autonomous row kernel. One warp per output row:
//   sref = h_refer[n] . att_ref        (coalesced, streaming-hint)
//   lane k: score_k = leaky(sref + hn[nei[n][k]])
//   warp softmax -> w_k
//   weighted gather, unrolled-by-4: one int4+float4 broadcast LDS per group,
//   4 independent LDG.128s batched per group (explicit MLP).
// ---------------------------------------------------------------------------
__global__ __launch_bounds__(256)
void gat_main(const int*   __restrict__ nei,
              const float* __restrict__ h,
              const float* __restrict__ h_refer,
              const float* __restrict__ att,
              float*       __restrict__ out,
              int N)
{
    __shared__ int   s_idx[8][KNEI];
    __shared__ float s_w[8][KNEI];

    const int warp = threadIdx.x >> 5;
    const int lane = threadIdx.x & 31;
    const int n    = blockIdx.x * 8 + warp;
    if (n >= N) return;

    // Reference-side dot (private to this row): coalesced 512B, read-once.
    const float4 aref = reinterpret_cast<const float4*>(att)[lane];
    const float4 hr   = __ldcs(&reinterpret_cast<const float4*>(
                                    h_refer + (size_t)n * D)[lane]);
    float sref = fmaf(hr.x, aref.x, fmaf(hr.y, aref.y,
                 fmaf(hr.z, aref.z, hr.w * aref.w)));
    #pragma unroll
    for (int o = 16; o; o >>= 1)
        sref += __shfl_xor_sync(0xffffffffu, sref, o);

    // Scores from precomputed hn (L2-hot 200 KB table).
    const int idx = __ldcs(&nei[(size_t)n * KNEI + lane]);   // 128B coalesced
    float s = sref + g_hn[idx];
    s = (s >= 0.0f) ? s : 0.01f * s;                         // leaky_relu(0.01)

    float m = s;
    #pragma unroll
    for (int o = 16; o; o >>= 1)
        m = fmaxf(m, __shfl_xor_sync(0xffffffffu, m, o));
    const float e = __expf(s - m);
    float sum = e;
    #pragma unroll
    for (int o = 16; o; o >>= 1)
        sum += __shfl_xor_sync(0xffffffffu, sum, o);

    s_w[warp][lane]   = e / sum;
    s_idx[warp][lane] = idx;
    __syncwarp();

    // Weighted gather: 4 independent rows per group, vectorized SMEM broadcast.
    float4 acc = make_float4(0.f, 0.f, 0.f, 0.f);
    #pragma unroll
    for (int kk = 0; kk < KNEI; kk += 4) {
        const int4   i4 = *reinterpret_cast<const int4*>(&s_idx[warp][kk]);
        const float4 w4 = *reinterpret_cast<const float4*>(&s_w[warp][kk]);
        const float4 v0 = reinterpret_cast<const float4*>(h + (size_t)i4.x * D)[lane];
        const float4 v1 = reinterpret_cast<const float4*>(h + (size_t)i4.y * D)[lane];
        const float4 v2 = reinterpret_cast<const float4*>(h + (size_t)i4.z * D)[lane];
        const float4 v3 = reinterpret_cast<const float4*>(h + (size_t)i4.w * D)[lane];
        acc.x = fmaf(w4.x, v0.x, acc.x); acc.y = fmaf(w4.x, v0.y, acc.y);
        acc.z = fmaf(w4.x, v0.z, acc.z); acc.w = fmaf(w4.x, v0.w, acc.w);
        acc.x = fmaf(w4.y, v1.x, acc.x); acc.y = fmaf(w4.y, v1.y, acc.y);
        acc.z = fmaf(w4.y, v1.z, acc.z); acc.w = fmaf(w4.y, v1.w, acc.w);
        acc.x = fmaf(w4.z, v2.x, acc.x); acc.y = fmaf(w4.z, v2.y, acc.y);
        acc.z = fmaf(w4.z, v2.z, acc.z); acc.w = fmaf(w4.z, v2.w, acc.w);
        acc.x = fmaf(w4.w, v3.x, acc.x); acc.y = fmaf(w4.w, v3.y, acc.y);
        acc.z = fmaf(w4.w, v3.z, acc.z); acc.w = fmaf(w4.w, v3.w, acc.w);
    }

    // Streaming store: output is never re-read — don't pollute L2.
    __stcs(&reinterpret_cast<float4*>(out + (size_t)n * D)[lane], acc);
}

extern "C" void kernel_launch(void* const* d_in, const int* in_sizes, int n_in,
                              void* d_out, int out_size)
{
    const int*   nei     = (const int*)d_in[0];    // int32 [N, 32]
    const float* h       = (const float*)d_in[1];  // f32   [M, 128]
    const float* h_refer = (const float*)d_in[2];  // f32   [N, 128]
    const float* att     = (const float*)d_in[3];  // f32   [1, 256]
    float*       out     = (float*)d_out;          // f32   [N, 128]

    const int N = in_sizes[0] / KNEI;
    const int M = in_sizes[1] / D;

    precompute_hn<<<(M + 7) / 8, 256>>>(h, att, M);
    gat_main<<<(N + 7) / 8, 256>>>(nei, h, h_refer, att, out, N);
}

// round 12
// speedup vs baseline: 2.6584x; 1.0358x over previous
#include <cuda_runtime.h>

#define D        128
#define KNEI     32
#define MAXROWS  50176   // >= M = 50000

// Scratch (no cudaMalloc allowed): precomputed neighbor-side row dots.
__device__ float g_hn[MAXROWS];   // hn[m] = h[m] . att[D..2D)

// ---------------------------------------------------------------------------
// Pass 1: hn[m] = h[m] . att_nei. One warp per row; streaming (~25.6 MB).
// ---------------------------------------------------------------------------
__global__ __launch_bounds__(256)
void precompute_hn(const float* __restrict__ h,
                   const float* __restrict__ att,
                   int M)
{
    const int gw   = (blockIdx.x * blockDim.x + threadIdx.x) >> 5;
    const int lane = threadIdx.x & 31;
    if (gw >= M) return;

    const float4 a = reinterpret_cast<const float4*>(att)[32 + lane];
    const float4 v = reinterpret_cast<const float4*>(h + (size_t)gw * D)[lane];

    float p = fmaf(v.x, a.x, fmaf(v.y, a.y, fmaf(v.z, a.z, v.w * a.w)));
    #pragma unroll
    for (int o = 16; o; o >>= 1)
        p += __shfl_xor_sync(0xffffffffu, p, o);
    if (lane == 0) g_hn[gw] = p;
}

// ---------------------------------------------------------------------------
// Pass 2: one warp per output row. Scores from precomputed hn; warp softmax;
// then the weighted gather runs as an explicit DEPTH-2 pipeline: two groups
// of 4 LDG.128 (8 loads) in flight per warp while FMAs drain the older group.
// __launch_bounds__(256, 4) raises the reg cap to 64 so ptxas keeps the
// pipeline in registers instead of collapsing it (R11 had regs=33, MLP~2).
// ---------------------------------------------------------------------------
__global__ __launch_bounds__(256, 4)
void gat_main(const int*   __restrict__ nei,
              const float* __restrict__ h,
              const float* __restrict__ h_refer,
              const float* __restrict__ att,
              float*       __restrict__ out,
              int N)
{
    __shared__ int   s_idx[8][KNEI];
    __shared__ float s_w[8][KNEI];

    const int warp = threadIdx.x >> 5;
    const int lane = threadIdx.x & 31;
    const int n    = blockIdx.x * 8 + warp;
    if (n >= N) return;

    // ---- score phase -------------------------------------------------------
    const float4 aref = reinterpret_cast<const float4*>(att)[lane];
    const float4 hr   = __ldcs(&reinterpret_cast<const float4*>(
                                    h_refer + (size_t)n * D)[lane]);
    float sref = fmaf(hr.x, aref.x, fmaf(hr.y, aref.y,
                 fmaf(hr.z, aref.z, hr.w * aref.w)));
    #pragma unroll
    for (int o = 16; o; o >>= 1)
        sref += __shfl_xor_sync(0xffffffffu, sref, o);

    const int idx = __ldcs(&nei[(size_t)n * KNEI + lane]);   // 128B coalesced
    float s = sref + g_hn[idx];                              // L1-hot 200KB table
    s = fmaxf(s, 0.01f * s);                                 // leaky_relu(0.01)

    float m = s;
    #pragma unroll
    for (int o = 16; o; o >>= 1)
        m = fmaxf(m, __shfl_xor_sync(0xffffffffu, m, o));
    const float e = __expf(s - m);
    float sum = e;
    #pragma unroll
    for (int o = 16; o; o >>= 1)
        sum += __shfl_xor_sync(0xffffffffu, sum, o);

    s_w[warp][lane]   = e / sum;
    s_idx[warp][lane] = idx;
    __syncwarp();

    // ---- weighted gather: depth-2 pipelined, 8 LDG.128 in flight ------------
    float4 acc = make_float4(0.f, 0.f, 0.f, 0.f);

    // group g covers neighbors 4g..4g+3
    int4   iA = *reinterpret_cast<const int4*>(&s_idx[warp][0]);
    float4 wA = *reinterpret_cast<const float4*>(&s_w[warp][0]);
    float4 a0 = reinterpret_cast<const float4*>(h + (size_t)iA.x * D)[lane];
    float4 a1 = reinterpret_cast<const float4*>(h + (size_t)iA.y * D)[lane];
    float4 a2 = reinterpret_cast<const float4*>(h + (size_t)iA.z * D)[lane];
    float4 a3 = reinterpret_cast<const float4*>(h + (size_t)iA.w * D)[lane];

    int4   iB = *reinterpret_cast<const int4*>(&s_idx[warp][4]);
    float4 wB = *reinterpret_cast<const float4*>(&s_w[warp][4]);
    float4 b0 = reinterpret_cast<const float4*>(h + (size_t)iB.x * D)[lane];
    float4 b1 = reinterpret_cast<const float4*>(h + (size_t)iB.y * D)[lane];
    float4 b2 = reinterpret_cast<const float4*>(h + (size_t)iB.z * D)[lane];
    float4 b3 = reinterpret_cast<const float4*>(h + (size_t)iB.w * D)[lane];

    #pragma unroll
    for (int g = 0; g < 8; ++g) {
        // consume buffer A (group g), then refill A from group g+2
        acc.x = fmaf(wA.x, a0.x, acc.x); acc.y = fmaf(wA.x, a0.y, acc.y);
        acc.z = fmaf(wA.x, a0.z, acc.z); acc.w = fmaf(wA.x, a0.w, acc.w);
        acc.x = fmaf(wA.y, a1.x, acc.x); acc.y = fmaf(wA.y, a1.y, acc.y);
        acc.z = fmaf(wA.y, a1.z, acc.z); acc.w = fmaf(wA.y, a1.w, acc.w);
        acc.x = fmaf(wA.z, a2.x, acc.x); acc.y = fmaf(wA.z, a2.y, acc.y);
        acc.z = fmaf(wA.z, a2.z, acc.z); acc.w = fmaf(wA.z, a2.w, acc.w);
        acc.x = fmaf(wA.w, a3.x, acc.x); acc.y = fmaf(wA.w, a3.y, acc.y);
        acc.z = fmaf(wA.w, a3.z, acc.z); acc.w = fmaf(wA.w, a3.w, acc.w);

        // rotate: A <- B (already in flight), B <- loads for group g+2
        wA = wB; a0 = b0; a1 = b1; a2 = b2; a3 = b3;
        if (g + 2 < 8) {
            iB = *reinterpret_cast<const int4*>(&s_idx[warp][(g + 2) * 4]);
            wB = *reinterpret_cast<const float4*>(&s_w[warp][(g + 2) * 4]);
            b0 = reinterpret_cast<const float4*>(h + (size_t)iB.x * D)[lane];
            b1 = reinterpret_cast<const float4*>(h + (size_t)iB.y * D)[lane];
            b2 = reinterpret_cast<const float4*>(h + (size_t)iB.z * D)[lane];
            b3 = reinterpret_cast<const float4*>(h + (size_t)iB.w * D)[lane];
        }
    }

    // Streaming store: output is never re-read.
    __stcs(&reinterpret_cast<float4*>(out + (size_t)n * D)[lane], acc);
}

extern "C" void kernel_launch(void* const* d_in, const int* in_sizes, int n_in,
                              void* d_out, int out_size)
{
    const int*   nei     = (const int*)d_in[0];    // int32 [N, 32]
    const float* h       = (const float*)d_in[1];  // f32   [M, 128]
    const float* h_refer = (const float*)d_in[2];  // f32   [N, 128]
    const float* att     = (const float*)d_in[3];  // f32   [1, 256]
    float*       out     = (float*)d_out;          // f32   [N, 128]

    const int N = in_sizes[0] / KNEI;
    const int M = in_sizes[1] / D;

    precompute_hn<<<(M + 7) / 8, 256>>>(h, att, M);
    gat_main<<<(N + 7) / 8, 256>>>(nei, h, h_refer, att, out, N);
}

// round 13
// speedup vs baseline: 3.3067x; 1.2439x over previous
#include <cuda_runtime.h>
#include <cuda_fp16.h>

#define D        128
#define KNEI     32
#define MAXROWS  50176   // >= M = 50000

// Scratch (no cudaMalloc allowed):
__device__ float   g_hn[MAXROWS];           // hn[m] = h[m] . att[D..2D)  (exact f32)
__device__ __half2 g_h16[MAXROWS * (D/2)];  // fp16 copy of h (12.8 MB) for the gather

// ---------------------------------------------------------------------------
// Pass 1: single read of h (25.6 MB): compute hn[m] AND write the fp16 copy.
// One warp per row; coalesced 512B read + 256B write per row.
// ---------------------------------------------------------------------------
__global__ __launch_bounds__(256)
void prep_h(const float* __restrict__ h,
            const float* __restrict__ att,
            int M)
{
    const int gw   = (blockIdx.x * blockDim.x + threadIdx.x) >> 5;
    const int lane = threadIdx.x & 31;
    if (gw >= M) return;

    const float4 a = reinterpret_cast<const float4*>(att)[32 + lane];
    const float4 v = reinterpret_cast<const float4*>(h + (size_t)gw * D)[lane];

    // fp16 copy (gather side only; scores below stay f32-exact)
    __half2 p0 = __floats2half2_rn(v.x, v.y);
    __half2 p1 = __floats2half2_rn(v.z, v.w);
    uint2 packed;
    packed.x = *reinterpret_cast<unsigned int*>(&p0);
    packed.y = *reinterpret_cast<unsigned int*>(&p1);
    reinterpret_cast<uint2*>(g_h16 + (size_t)gw * (D/2))[lane] = packed;

    float p = fmaf(v.x, a.x, fmaf(v.y, a.y, fmaf(v.z, a.z, v.w * a.w)));
    #pragma unroll
    for (int o = 16; o; o >>= 1)
        p += __shfl_xor_sync(0xffffffffu, p, o);
    if (lane == 0) g_hn[gw] = p;
}

// ---------------------------------------------------------------------------
// Pass 2: one warp per output row. Scores from f32 g_hn (exact); warp softmax;
// weighted gather from the fp16 table (256B/row-read, half of R12's traffic).
// Depth-2 pipeline of 8-wide load groups: 16 LDG.64 in flight per warp.
// ---------------------------------------------------------------------------
__global__ __launch_bounds__(256, 4)
void gat_main(const int*   __restrict__ nei,
              const float* __restrict__ h_refer,
              const float* __restrict__ att,
              float*       __restrict__ out,
              int N)
{
    __shared__ int   s_idx[8][KNEI];
    __shared__ float s_w[8][KNEI];

    const int warp = threadIdx.x >> 5;
    const int lane = threadIdx.x & 31;
    const int n    = blockIdx.x * 8 + warp;
    if (n >= N) return;

    // ---- score phase (f32-exact, identical weights to the f32 kernel) ------
    const float4 aref = reinterpret_cast<const float4*>(att)[lane];
    const float4 hr   = __ldcs(&reinterpret_cast<const float4*>(
                                    h_refer + (size_t)n * D)[lane]);
    float sref = fmaf(hr.x, aref.x, fmaf(hr.y, aref.y,
                 fmaf(hr.z, aref.z, hr.w * aref.w)));
    #pragma unroll
    for (int o = 16; o; o >>= 1)
        sref += __shfl_xor_sync(0xffffffffu, sref, o);

    const int idx = __ldcs(&nei[(size_t)n * KNEI + lane]);   // 128B coalesced
    float s = sref + g_hn[idx];
    s = fmaxf(s, 0.01f * s);                                 // leaky_relu(0.01)

    float m = s;
    #pragma unroll
    for (int o = 16; o; o >>= 1)
        m = fmaxf(m, __shfl_xor_sync(0xffffffffu, m, o));
    const float e = __expf(s - m);
    float sum = e;
    #pragma unroll
    for (int o = 16; o; o >>= 1)
        sum += __shfl_xor_sync(0xffffffffu, sum, o);

    s_w[warp][lane]   = e / sum;
    s_idx[warp][lane] = idx;
    __syncwarp();

    // ---- weighted gather: fp16 rows, depth-2 pipeline of 8-wide groups -----
    float4 acc = make_float4(0.f, 0.f, 0.f, 0.f);
    uint2 bufA[8], bufB[8];
    float wTabA[8], wTabB[8];

    #pragma unroll
    for (int j = 0; j < 8; ++j) {
        const int ii = s_idx[warp][j];
        wTabA[j] = s_w[warp][j];
        bufA[j]  = reinterpret_cast<const uint2*>(g_h16 + (size_t)ii * (D/2))[lane];
    }
    #pragma unroll
    for (int j = 0; j < 8; ++j) {
        const int ii = s_idx[warp][8 + j];
        wTabB[j] = s_w[warp][8 + j];
        bufB[j]  = reinterpret_cast<const uint2*>(g_h16 + (size_t)ii * (D/2))[lane];
    }

    #pragma unroll
    for (int g = 0; g < 4; ++g) {
        // consume bufA (group g)
        #pragma unroll
        for (int j = 0; j < 8; ++j) {
            const __half2 h0 = *reinterpret_cast<const __half2*>(&bufA[j].x);
            const __half2 h1 = *reinterpret_cast<const __half2*>(&bufA[j].y);
            const float2 f0 = __half22float2(h0);
            const float2 f1 = __half22float2(h1);
            const float wk = wTabA[j];
            acc.x = fmaf(wk, f0.x, acc.x);
            acc.y = fmaf(wk, f0.y, acc.y);
            acc.z = fmaf(wk, f1.x, acc.z);
            acc.w = fmaf(wk, f1.y, acc.w);
        }
        // rotate: A <- B (in flight), B <- group g+2
        #pragma unroll
        for (int j = 0; j < 8; ++j) { bufA[j] = bufB[j]; wTabA[j] = wTabB[j]; }
        if (g + 2 < 4) {
            const int base = (g + 2) * 8;
            #pragma unroll
            for (int j = 0; j < 8; ++j) {
                const int ii = s_idx[warp][base + j];
                wTabB[j] = s_w[warp][base + j];
                bufB[j]  = reinterpret_cast<const uint2*>(
                               g_h16 + (size_t)ii * (D/2))[lane];
            }
        }
    }

    // Streaming store: output is never re-read.
    __stcs(&reinterpret_cast<float4*>(out + (size_t)n * D)[lane], acc);
}

extern "C" void kernel_launch(void* const* d_in, const int* in_sizes, int n_in,
                              void* d_out, int out_size)
{
    const int*   nei     = (const int*)d_in[0];    // int32 [N, 32]
    const float* h       = (const float*)d_in[1];  // f32   [M, 128]
    const float* h_refer = (const float*)d_in[2];  // f32   [N, 128]
    const float* att     = (const float*)d_in[3];  // f32   [1, 256]
    float*       out     = (float*)d_out;          // f32   [N, 128]

    const int N = in_sizes[0] / KNEI;
    const int M = in_sizes[1] / D;

    prep_h<<<(M + 7) / 8, 256>>>(h, att, M);
    gat_main<<<(N + 7) / 8, 256>>>(nei, h_refer, att, out, N);
}

// round 14
// speedup vs baseline: 3.5028x; 1.0593x over previous
#include <cuda_runtime.h>
#include <cuda_fp16.h>

#define D        128
#define KNEI     32
#define MAXROWS  50176   // >= M = 50000

// Scratch (no cudaMalloc allowed):
__device__ float   g_hn[MAXROWS];           // hn[m] = h[m] . att[D..2D)  (exact f32)
__device__ __half2 g_h16[MAXROWS * (D/2)];  // fp16 copy of h (12.8 MB) for the gather

// ---------------------------------------------------------------------------
// Pass 1: single read of h (25.6 MB): compute hn[m] AND write the fp16 copy.
// ---------------------------------------------------------------------------
__global__ __launch_bounds__(256)
void prep_h(const float* __restrict__ h,
            const float* __restrict__ att,
            int M)
{
    const int gw   = (blockIdx.x * blockDim.x + threadIdx.x) >> 5;
    const int lane = threadIdx.x & 31;
    if (gw >= M) return;

    const float4 a = reinterpret_cast<const float4*>(att)[32 + lane];
    const float4 v = reinterpret_cast<const float4*>(h + (size_t)gw * D)[lane];

    __half2 p0 = __floats2half2_rn(v.x, v.y);
    __half2 p1 = __floats2half2_rn(v.z, v.w);
    uint2 packed;
    packed.x = *reinterpret_cast<unsigned int*>(&p0);
    packed.y = *reinterpret_cast<unsigned int*>(&p1);
    reinterpret_cast<uint2*>(g_h16 + (size_t)gw * (D/2))[lane] = packed;

    float p = fmaf(v.x, a.x, fmaf(v.y, a.y, fmaf(v.z, a.z, v.w * a.w)));
    #pragma unroll
    for (int o = 16; o; o >>= 1)
        p += __shfl_xor_sync(0xffffffffu, p, o);
    if (lane == 0) g_hn[gw] = p;
}

// ---------------------------------------------------------------------------
// Pass 2: one warp per output row. f32-exact scores -> warp softmax -> fp16
// weighted gather (depth-2 pipeline, 16 LDG.64 in flight). Weighted sum uses
// packed fma.rn.f32x2 (FFMA2): 2 packed FMAs per neighbor instead of 4 scalar.
// Weights are re-read from SMEM at consume time (frees 16 regs vs R13),
// and __launch_bounds__(256,5) caps regs at 51 for a 5th resident block.
// ---------------------------------------------------------------------------
__global__ __launch_bounds__(256, 5)
void gat_main(const int*   __restrict__ nei,
              const float* __restrict__ h_refer,
              const float* __restrict__ att,
              float*       __restrict__ out,
              int N)
{
    __shared__ int   s_idx[8][KNEI];
    __shared__ float s_w[8][KNEI];

    const int warp = threadIdx.x >> 5;
    const int lane = threadIdx.x & 31;
    const int n    = blockIdx.x * 8 + warp;
    if (n >= N) return;

    // ---- score phase (f32-exact) -------------------------------------------
    const float4 aref = reinterpret_cast<const float4*>(att)[lane];
    const float4 hr   = __ldcs(&reinterpret_cast<const float4*>(
                                    h_refer + (size_t)n * D)[lane]);
    float sref = fmaf(hr.x, aref.x, fmaf(hr.y, aref.y,
                 fmaf(hr.z, aref.z, hr.w * aref.w)));
    #pragma unroll
    for (int o = 16; o; o >>= 1)
        sref += __shfl_xor_sync(0xffffffffu, sref, o);

    const int idx = __ldcs(&nei[(size_t)n * KNEI + lane]);   // 128B coalesced
    float s = sref + g_hn[idx];
    s = fmaxf(s, 0.01f * s);                                 // leaky_relu(0.01)

    float m = s;
    #pragma unroll
    for (int o = 16; o; o >>= 1)
        m = fmaxf(m, __shfl_xor_sync(0xffffffffu, m, o));
    const float e = __expf(s - m);
    float sum = e;
    #pragma unroll
    for (int o = 16; o; o >>= 1)
        sum += __shfl_xor_sync(0xffffffffu, sum, o);

    s_w[warp][lane]   = e / sum;
    s_idx[warp][lane] = idx;
    __syncwarp();

    // ---- weighted gather: fp16 rows, depth-2 pipeline, FFMA2 accumulate ----
    unsigned long long acc01 = 0ull, acc23 = 0ull;   // packed f32x2 accumulators
    uint2 bufA[8], bufB[8];

    #pragma unroll
    for (int j = 0; j < 8; ++j)
        bufA[j] = reinterpret_cast<const uint2*>(
                      g_h16 + (size_t)s_idx[warp][j] * (D/2))[lane];
    #pragma unroll
    for (int j = 0; j < 8; ++j)
        bufB[j] = reinterpret_cast<const uint2*>(
                      g_h16 + (size_t)s_idx[warp][8 + j] * (D/2))[lane];

    #pragma unroll
    for (int g = 0; g < 4; ++g) {
        const float4 wlo = *reinterpret_cast<const float4*>(&s_w[warp][g * 8]);
        const float4 whi = *reinterpret_cast<const float4*>(&s_w[warp][g * 8 + 4]);
        const float wk[8] = { wlo.x, wlo.y, wlo.z, wlo.w,
                              whi.x, whi.y, whi.z, whi.w };
        #pragma unroll
        for (int j = 0; j < 8; ++j) {
            const float2 f0 = __half22float2(*reinterpret_cast<const __half2*>(&bufA[j].x));
            const float2 f1 = __half22float2(*reinterpret_cast<const __half2*>(&bufA[j].y));
            unsigned long long v01, v23, ww;
            asm("mov.b64 %0, {%1,%2};" : "=l"(v01) : "f"(f0.x), "f"(f0.y));
            asm("mov.b64 %0, {%1,%2};" : "=l"(v23) : "f"(f1.x), "f"(f1.y));
            asm("mov.b64 %0, {%1,%2};" : "=l"(ww)  : "f"(wk[j]), "f"(wk[j]));
            asm("fma.rn.f32x2 %0, %1, %2, %0;" : "+l"(acc01) : "l"(v01), "l"(ww));
            asm("fma.rn.f32x2 %0, %1, %2, %0;" : "+l"(acc23) : "l"(v23), "l"(ww));
        }
        // rotate: A <- B (in flight), B <- group g+2
        #pragma unroll
        for (int j = 0; j < 8; ++j) bufA[j] = bufB[j];
        if (g + 2 < 4) {
            const int base = (g + 2) * 8;
            #pragma unroll
            for (int j = 0; j < 8; ++j)
                bufB[j] = reinterpret_cast<const uint2*>(
                              g_h16 + (size_t)s_idx[warp][base + j] * (D/2))[lane];
        }
    }

    float4 acc;
    asm("mov.b64 {%0,%1}, %2;" : "=f"(acc.x), "=f"(acc.y) : "l"(acc01));
    asm("mov.b64 {%0,%1}, %2;" : "=f"(acc.z), "=f"(acc.w) : "l"(acc23));

    // Streaming store: output is never re-read.
    __stcs(&reinterpret_cast<float4*>(out + (size_t)n * D)[lane], acc);
}

extern "C" void kernel_launch(void* const* d_in, const int* in_sizes, int n_in,
                              void* d_out, int out_size)
{
    const int*   nei     = (const int*)d_in[0];    // int32 [N, 32]
    const float* h       = (const float*)d_in[1];  // f32   [M, 128]
    const float* h_refer = (const float*)d_in[2];  // f32   [N, 128]
    const float* att     = (const float*)d_in[3];  // f32   [1, 256]
    float*       out     = (float*)d_out;          // f32   [N, 128]

    const int N = in_sizes[0] / KNEI;
    const int M = in_sizes[1] / D;

    prep_h<<<(M + 7) / 8, 256>>>(h, att, M);
    gat_main<<<(N + 7) / 8, 256>>>(nei, h_refer, att, out, N);
}